// round 2
// baseline (speedup 1.0000x reference)
#include <cuda_runtime.h>
#include <math.h>

#define BB 16
#define LL 2048
#define DD 512
#define EE 8
#define HH 8
#define EHD 64
#define FF 2048

typedef unsigned long long u64;

// ------------- scratch (static device arrays; no allocation) -------------
__device__ float g_xn[BB*DD];
__device__ float g_qn[BB*EE*DD];
__device__ float g_gates[BB*EE];
__device__ float g_qh[BB*EE*DD];
__device__ float g_qt[BB*EHD*DD];
__device__ float g_scores[BB*EHD*LL];
__device__ float g_ent[BB*EE];
__device__ float g_cpart[4*BB*EHD*DD];
__device__ float g_attn[BB*EE*DD];
__device__ float g_ao[BB*EE*DD];
__device__ float g_x[BB*EE*DD];
__device__ float g_xo[BB*EE*DD];
__device__ float g_h[BB*EE*FF];
__device__ float g_y[BB*EE*DD];

// ------------- f32x2 helpers -------------
__device__ __forceinline__ u64 pack2(float x, float y) {
    u64 r; asm("mov.b64 %0, {%1, %2};" : "=l"(r) : "f"(x), "f"(y)); return r;
}
__device__ __forceinline__ void fma2(u64 &d, u64 a, u64 b) {
    asm("fma.rn.f32x2 %0, %1, %2, %3;" : "=l"(d) : "l"(a), "l"(b), "l"(d));
}
__device__ __forceinline__ float2 unpack2(u64 v) {
    float2 f; asm("mov.b64 {%0, %1}, %2;" : "=f"(f.x), "=f"(f.y) : "l"(v)); return f;
}

// ------------- block reductions -------------
template<int NT>
__device__ __forceinline__ float blkSum(float v) {
    __shared__ float sh[NT/32];
    int lane = threadIdx.x & 31, w = threadIdx.x >> 5;
    #pragma unroll
    for (int o = 16; o; o >>= 1) v += __shfl_down_sync(0xffffffffu, v, o);
    __syncthreads();
    if (!lane) sh[w] = v;
    __syncthreads();
    if (!w) {
        float x = (lane < NT/32) ? sh[lane] : 0.f;
        #pragma unroll
        for (int o = 16; o; o >>= 1) x += __shfl_down_sync(0xffffffffu, x, o);
        if (!lane) sh[0] = x;
    }
    __syncthreads();
    return sh[0];
}
template<int NT>
__device__ __forceinline__ float blkMax(float v) {
    __shared__ float sh[NT/32];
    int lane = threadIdx.x & 31, w = threadIdx.x >> 5;
    #pragma unroll
    for (int o = 16; o; o >>= 1) v = fmaxf(v, __shfl_down_sync(0xffffffffu, v, o));
    __syncthreads();
    if (!lane) sh[w] = v;
    __syncthreads();
    if (!w) {
        float x = (lane < NT/32) ? sh[lane] : -1e30f;
        #pragma unroll
        for (int o = 16; o; o >>= 1) x = fmaxf(x, __shfl_down_sync(0xffffffffu, x, o));
        if (!lane) sh[0] = x;
    }
    __syncthreads();
    return sh[0];
}

// ------------- 1) LN stats of query + gates softmax -------------
__global__ void k_prep(const float* __restrict__ q, const float* __restrict__ wg) {
    int b = blockIdx.x, t = threadIdx.x;           // 16 blocks x 512
    float v = q[b*DD + t];
    float mu  = blkSum<512>(v)   * (1.f/DD);
    float msq = blkSum<512>(v*v) * (1.f/DD);
    float rs = rsqrtf(msq - mu*mu + 1e-5f);
    g_xn[b*DD + t] = (v - mu) * rs;

    float le[EE];
    #pragma unroll
    for (int e = 0; e < EE; ++e) le[e] = v * wg[t*EE + e];
    #pragma unroll
    for (int e = 0; e < EE; ++e)
        #pragma unroll
        for (int o = 16; o; o >>= 1) le[e] += __shfl_down_sync(0xffffffffu, le[e], o);
    __shared__ float sge[16][EE];
    int lane = t & 31, w = t >> 5;
    if (!lane)
        #pragma unroll
        for (int e = 0; e < EE; ++e) sge[w][e] = le[e];
    __syncthreads();
    if (t == 0) {
        float lg[EE];
        #pragma unroll
        for (int e = 0; e < EE; ++e) {
            float s = 0.f;
            #pragma unroll
            for (int w2 = 0; w2 < 16; ++w2) s += sge[w2][e];
            lg[e] = s;
        }
        float m = lg[0];
        #pragma unroll
        for (int e = 1; e < EE; ++e) m = fmaxf(m, lg[e]);
        float s = 0.f, ex[EE];
        #pragma unroll
        for (int e = 0; e < EE; ++e) { ex[e] = expf(lg[e] - m); s += ex[e]; }
        float inv = 1.f / s;
        #pragma unroll
        for (int e = 0; e < EE; ++e) g_gates[b*EE + e] = ex[e] * inv;
    }
}

// ------------- 1b) qn = xn * g + b per expert -------------
__global__ void k_qn(const float* __restrict__ g, const float* __restrict__ bb) {
    int blk = blockIdx.x, t = threadIdx.x;         // 128 blocks x 512
    int b = blk >> 3, e = blk & 7;
    g_qn[(b*EE+e)*DD + t] = g_xn[b*DD + t] * g[e*DD + t] + bb[e*DD + t];
}

// ------------- generic (B,E,K)x(E,K,N) GEMM, 64-col tiles -------------
__global__ void __launch_bounds__(256) k_gemm(
        const float* __restrict__ X, const float* __restrict__ W,
        const float* __restrict__ bias, const float* __restrict__ resid,
        float* __restrict__ Y, int K, int N, int act) {
    int n0 = blockIdx.x * 64, e = blockIdx.y, t = threadIdx.x;
    __shared__ float sX[16][65];
    __shared__ float sW[64][65];
    int c = t & 63, rg = t >> 6;                   // 64 cols x 4 rowgroups x 4 rows
    float acc[4] = {0,0,0,0};
    for (int k0 = 0; k0 < K; k0 += 64) {
        for (int i = t; i < 1024; i += 256) {
            int b = i >> 6, kk = i & 63;
            sX[b][kk] = X[(b*EE + e)*K + k0 + kk];
        }
        for (int i = t; i < 4096; i += 256) {
            int kk = i >> 6, n = i & 63;
            sW[kk][n] = W[((size_t)e*K + k0 + kk)*N + n0 + n];
        }
        __syncthreads();
        #pragma unroll 8
        for (int kk = 0; kk < 64; ++kk) {
            float w = sW[kk][c];
            #pragma unroll
            for (int j = 0; j < 4; ++j) acc[j] = fmaf(sX[rg*4+j][kk], w, acc[j]);
        }
        __syncthreads();
    }
    int n = n0 + c;
    float bi = bias[e*N + n];
    #pragma unroll
    for (int j = 0; j < 4; ++j) {
        int b = rg*4 + j;
        float o = acc[j] + bi;
        if (act == 1) o = 0.5f * o * (1.f + erff(o * 0.70710678118654752f));
        if (resid) o += resid[(b*EE + e)*N + n];
        Y[(b*EE + e)*N + n] = o;
    }
}

// ------------- 3) q~[b,eh,d] = (1/8) sum_c qh[b,e,h*64+c] * Wk[e,d,h*64+c] -------------
__global__ void __launch_bounds__(256) k_qt(const float* __restrict__ Wk) {
    int e = blockIdx.x >> 3, h = blockIdx.x & 7, t = threadIdx.x; // 64 blocks x 256
    __shared__ float sQ[16][64];
    __shared__ float sW[128][65];
    for (int i = t; i < 1024; i += 256) {
        int b = i >> 6, cc = i & 63;
        sQ[b][cc] = g_qh[(b*EE + e)*DD + h*64 + cc];
    }
    int dd = t & 127, bg = t >> 7;                 // 128 d x 2 groups of 8 rows
    for (int d0 = 0; d0 < DD; d0 += 128) {
        __syncthreads();
        for (int i = t; i < 8192; i += 256) {
            int dr = i >> 6, cc = i & 63;
            sW[dr][cc] = Wk[((size_t)e*DD + d0 + dr)*DD + h*64 + cc];
        }
        __syncthreads();
        float acc[8] = {0,0,0,0,0,0,0,0};
        #pragma unroll 8
        for (int cc = 0; cc < 64; ++cc) {
            float w = sW[dd][cc];
            #pragma unroll
            for (int j = 0; j < 8; ++j) acc[j] += sQ[bg*8+j][cc] * w;
        }
        #pragma unroll
        for (int j = 0; j < 8; ++j) {
            int b = bg*8 + j;
            g_qt[((size_t)b*EHD + e*8 + h)*DD + d0 + dd] = 0.125f * acc[j];
        }
    }
}

// ------------- 4) scores[b,eh,l] = retr[b,l,:] . qt[b,eh,:] -------------
__global__ void __launch_bounds__(128) k_scores(const float* __restrict__ retr) {
    int lb = blockIdx.x, b = blockIdx.y, t = threadIdx.x;   // (16,16) x 128
    int l0 = lb * 128;
    __shared__ float sA[128][33];
    __shared__ __align__(16) float sB[32][66];
    int lg = t & 15, eg = t >> 4;
    u64 acc[8][4];
    #pragma unroll
    for (int i = 0; i < 8; ++i)
        #pragma unroll
        for (int m = 0; m < 4; ++m) acc[i][m] = 0ull;

    for (int kt = 0; kt < 16; ++kt) {
        int d0 = kt * 32;
        int kk = t & 31, lr = t >> 5;
        #pragma unroll
        for (int r = 0; r < 32; ++r) {
            int l = lr + 4*r;
            sA[l][kk] = retr[((size_t)b*LL + l0 + l)*DD + d0 + kk];
        }
        #pragma unroll
        for (int r = 0; r < 16; ++r) {
            int eh = lr + 4*r;
            sB[kk][eh] = g_qt[((size_t)b*EHD + eh)*DD + d0 + kk];
        }
        __syncthreads();
        #pragma unroll 4
        for (int k2 = 0; k2 < 32; ++k2) {
            u64 bb[4];
            #pragma unroll
            for (int m = 0; m < 4; ++m)
                bb[m] = *reinterpret_cast<const u64*>(&sB[k2][2*eg + 16*m]);
            #pragma unroll
            for (int i = 0; i < 8; ++i) {
                float a = sA[lg + 16*i][k2];
                u64 aa = pack2(a, a);
                #pragma unroll
                for (int m = 0; m < 4; ++m) fma2(acc[i][m], aa, bb[m]);
            }
        }
        __syncthreads();
    }
    #pragma unroll
    for (int i = 0; i < 8; ++i) {
        int l = l0 + lg + 16*i;
        #pragma unroll
        for (int m = 0; m < 4; ++m) {
            float2 v = unpack2(acc[i][m]);
            int eh = 2*eg + 16*m;
            g_scores[((size_t)b*EHD + eh    )*LL + l] = v.x;
            g_scores[((size_t)b*EHD + eh + 1)*LL + l] = v.y;
        }
    }
}

// ------------- 5) softmax over L, in place -------------
__global__ void k_softmax() {
    int r = blockIdx.x, t = threadIdx.x;           // 1024 blocks x 256
    float* base = g_scores + (size_t)r * LL;
    float v[8];
    #pragma unroll
    for (int i = 0; i < 8; ++i) v[i] = base[t + 256*i];
    float m = v[0];
    #pragma unroll
    for (int i = 1; i < 8; ++i) m = fmaxf(m, v[i]);
    m = blkMax<256>(m);
    float s = 0.f;
    #pragma unroll
    for (int i = 0; i < 8; ++i) { v[i] = expf(v[i] - m); s += v[i]; }
    s = blkSum<256>(s);
    float inv = 1.f / s;
    #pragma unroll
    for (int i = 0; i < 8; ++i) base[t + 256*i] = v[i] * inv;
}

// ------------- 6) entropy of head-averaged probs -------------
__global__ void k_entropy() {
    int be = blockIdx.x, t = threadIdx.x;          // 128 blocks x 256
    int b = be >> 3, e = be & 7;
    const float* base = g_scores + (((size_t)b*EHD) + e*8) * LL;
    float acc = 0.f;
    for (int l = t; l < LL; l += 256) {
        float s = 0.f;
        #pragma unroll
        for (int h = 0; h < HH; ++h) s += base[(size_t)h*LL + l];
        float p = fmaxf(s * 0.125f, 1e-12f);
        acc += p * __logf(p);
    }
    acc = blkSum<256>(acc);
    if (t == 0) g_ent[be] = -acc;
}

// ------------- 7) ctx partials: cpart[lc][b][eh][d] = sum_{l in chunk} probs*retr -------------
__global__ void __launch_bounds__(256) k_ctx(const float* __restrict__ retr) {
    int d0 = blockIdx.x * 128, b = blockIdx.y, lc = blockIdx.z, t = threadIdx.x; // (4,16,4) x 256
    __shared__ float sP[64][33];
    __shared__ __align__(16) float sR[32][130];
    int dg = t & 31, ehg = t >> 5;                 // 32 d-groups(4d) x 8 eh-groups(8eh)
    u64 acc[8][2];
    #pragma unroll
    for (int i = 0; i < 8; ++i) { acc[i][0] = 0ull; acc[i][1] = 0ull; }

    for (int kt = 0; kt < 16; ++kt) {
        int lbase = lc*512 + kt*32;
        for (int i = t; i < 2048; i += 256) {
            int eh = i >> 5, ll = i & 31;
            sP[eh][ll] = g_scores[((size_t)b*EHD + eh)*LL + lbase + ll];
        }
        for (int i = t; i < 4096; i += 256) {
            int ll = i >> 7, dd = i & 127;
            sR[ll][dd] = retr[((size_t)b*LL + lbase + ll)*DD + d0 + dd];
        }
        __syncthreads();
        #pragma unroll 4
        for (int l2 = 0; l2 < 32; ++l2) {
            u64 b0 = *reinterpret_cast<const u64*>(&sR[l2][4*dg]);
            u64 b1 = *reinterpret_cast<const u64*>(&sR[l2][4*dg + 2]);
            #pragma unroll
            for (int i = 0; i < 8; ++i) {
                float a = sP[ehg*8 + i][l2];
                u64 aa = pack2(a, a);
                fma2(acc[i][0], aa, b0);
                fma2(acc[i][1], aa, b1);
            }
        }
        __syncthreads();
    }
    #pragma unroll
    for (int i = 0; i < 8; ++i) {
        int eh = ehg*8 + i;
        float2 v0 = unpack2(acc[i][0]), v1 = unpack2(acc[i][1]);
        float* p = g_cpart + (((size_t)lc*BB + b)*EHD + eh)*DD + d0 + 4*dg;
        p[0] = v0.x; p[1] = v0.y; p[2] = v1.x; p[3] = v1.y;
    }
}

// ------------- 8) attn[b,e,h*64+c] = sum_d ctx * Wv[e,d,h*64+c] + bv -------------
__global__ void __launch_bounds__(256) k_attnproj(const float* __restrict__ Wv,
                                                  const float* __restrict__ bv) {
    int e = blockIdx.x >> 3, h = blockIdx.x & 7, t = threadIdx.x; // 64 blocks x 256
    __shared__ float sC[16][65];
    __shared__ float sW[64][65];
    int c = t & 63, rg = t >> 6;
    float acc[4] = {0,0,0,0};
    int eh = e*8 + h;
    for (int d0 = 0; d0 < DD; d0 += 64) {
        for (int i = t; i < 1024; i += 256) {
            int b = i >> 6, dd = i & 63;
            float s = 0.f;
            #pragma unroll
            for (int lcx = 0; lcx < 4; ++lcx)
                s += g_cpart[(((size_t)lcx*BB + b)*EHD + eh)*DD + d0 + dd];
            sC[b][dd] = s;
        }
        for (int i = t; i < 4096; i += 256) {
            int dd = i >> 6, cc = i & 63;
            sW[dd][cc] = Wv[((size_t)e*DD + d0 + dd)*DD + h*64 + cc];
        }
        __syncthreads();
        #pragma unroll 8
        for (int dd = 0; dd < 64; ++dd) {
            float w = sW[dd][c];
            #pragma unroll
            for (int j = 0; j < 4; ++j) acc[j] += sC[rg*4+j][dd] * w;
        }
        __syncthreads();
    }
    float bi = bv[e*DD + h*64 + c];
    #pragma unroll
    for (int j = 0; j < 4; ++j) {
        int b = rg*4 + j;
        g_attn[((size_t)b*EE + e)*DD + h*64 + c] = acc[j] + bi;
    }
}

// ------------- 9) x = query + attn_out ; xo = LN(x) affine -------------
__global__ void k_xln(const float* __restrict__ q, const float* __restrict__ g,
                      const float* __restrict__ bb) {
    int blk = blockIdx.x, t = threadIdx.x;         // 128 blocks x 512
    int b = blk >> 3, e = blk & 7;
    float x = q[b*DD + t] + g_ao[((size_t)b*EE + e)*DD + t];
    g_x[((size_t)b*EE + e)*DD + t] = x;
    float mu  = blkSum<512>(x)   * (1.f/DD);
    float msq = blkSum<512>(x*x) * (1.f/DD);
    float rs = rsqrtf(msq - mu*mu + 1e-5f);
    g_xo[((size_t)b*EE + e)*DD + t] = (x - mu) * rs * g[e*DD + t] + bb[e*DD + t];
}

// ------------- 12) gating mix + write output -------------
__global__ void k_final(const float* __restrict__ y, float* __restrict__ out, int out_size) {
    int b = blockIdx.x, t = threadIdx.x;           // 16 blocks x 512
    __shared__ float sgt[EE];
    if (t == 0) {
        float gt[EE], s = 0.f;
        #pragma unroll
        for (int e = 0; e < EE; ++e) {
            gt[e] = g_gates[b*EE + e] * expf(-0.5f * g_ent[b*EE + e]);
            s += gt[e];
        }
        float inv = 1.f / (s + 1e-9f);
        #pragma unroll
        for (int e = 0; e < EE; ++e) sgt[e] = gt[e] * inv;
    }
    __syncthreads();
    float m = 0.f;
    #pragma unroll
    for (int e = 0; e < EE; ++e) m += sgt[e] * y[((size_t)b*EE + e)*DD + t];
    out[b*DD + t] = m;                              // fused (ALPHA=1)
    if (out_size >= BB*DD + BB*EE*DD + BB*EE) {
        if (t < EE) out[BB*DD + BB*EE*DD + b*EE + t] = sgt[t];
    }
}

// ------------- host -------------
extern "C" void kernel_launch(void* const* d_in, const int* in_sizes, int n_in,
                              void* d_out, int out_size) {
    const float* query = (const float*)d_in[0];
    const float* retr  = (const float*)d_in[1];
    const float* wgate = (const float*)d_in[2];
    const float* lnqg  = (const float*)d_in[3];
    const float* lnqb  = (const float*)d_in[4];
    const float* Wq    = (const float*)d_in[5];
    const float* bq    = (const float*)d_in[6];
    const float* Wk    = (const float*)d_in[7];
    const float* Wv    = (const float*)d_in[9];
    const float* bv    = (const float*)d_in[10];
    const float* Wo    = (const float*)d_in[11];
    const float* bo    = (const float*)d_in[12];
    const float* lnog  = (const float*)d_in[13];
    const float* lnob  = (const float*)d_in[14];
    const float* W1    = (const float*)d_in[15];
    const float* b1    = (const float*)d_in[16];
    const float* W2    = (const float*)d_in[17];
    const float* b2    = (const float*)d_in[18];
    float* out = (float*)d_out;

    void *p_qn, *p_qh, *p_attn, *p_ao, *p_x, *p_xo, *p_h, *p_y;
    cudaGetSymbolAddress(&p_qn, g_qn);
    cudaGetSymbolAddress(&p_qh, g_qh);
    cudaGetSymbolAddress(&p_attn, g_attn);
    cudaGetSymbolAddress(&p_ao, g_ao);
    cudaGetSymbolAddress(&p_x, g_x);
    cudaGetSymbolAddress(&p_xo, g_xo);
    cudaGetSymbolAddress(&p_h, g_h);
    cudaGetSymbolAddress(&p_y, g_y);
    float* yptr = (out_size >= BB*DD + BB*EE*DD) ? (out + BB*DD) : (float*)p_y;

    k_prep<<<BB, 512>>>(query, wgate);
    k_qn<<<BB*EE, 512>>>(lnqg, lnqb);
    k_gemm<<<dim3(8, EE), 256>>>((const float*)p_qn, Wq, bq, nullptr, (float*)p_qh, DD, DD, 0);
    k_qt<<<EE*HH, 256>>>(Wk);
    k_scores<<<dim3(16, BB), 128>>>(retr);
    k_softmax<<<BB*EHD, 256>>>();
    k_entropy<<<BB*EE, 256>>>();
    k_ctx<<<dim3(4, BB, 4), 256>>>(retr);
    k_attnproj<<<EE*HH, 256>>>(Wv, bv);
    k_gemm<<<dim3(8, EE), 256>>>((const float*)p_attn, Wo, bo, nullptr, (float*)p_ao, DD, DD, 0);
    k_xln<<<BB*EE, 512>>>(query, lnog, lnob);
    k_gemm<<<dim3(32, EE), 256>>>((const float*)p_xo, W1, b1, nullptr, (float*)p_h, DD, FF, 1);
    k_gemm<<<dim3(8, EE), 256>>>((const float*)p_h, W2, b2, (const float*)p_x, yptr, FF, DD, 0);
    k_final<<<BB, 512>>>(yptr, out, out_size);
}

// round 4
// speedup vs baseline: 1.1611x; 1.1611x over previous
#include <cuda_runtime.h>
#include <math.h>

#define BB 16
#define LL 2048
#define DD 512
#define EE 8
#define HH 8
#define EHD 64
#define FF 2048

typedef unsigned long long u64;

// ------------- scratch -------------
__device__ float g_xn[BB*DD];
__device__ float g_qn[BB*EE*DD];
__device__ float g_gates[BB*EE];
__device__ float g_qh[BB*EE*DD];
__device__ float g_qt[BB*EHD*DD];
__device__ float g_scores[BB*EHD*LL];
__device__ float g_ent[BB*EE];
__device__ float g_cpart[4*BB*EHD*DD];
__device__ float g_ctx[BB*EHD*DD];
__device__ float g_attn[BB*EE*DD];
__device__ float g_ao[BB*EE*DD];
__device__ float g_x[BB*EE*DD];
__device__ float g_xo[BB*EE*DD];
__device__ float g_h[BB*EE*FF];
__device__ float g_y[BB*EE*DD];
__device__ float g_part[2200000];

// ------------- f32x2 helpers -------------
__device__ __forceinline__ u64 pack2(float x, float y) {
    u64 r; asm("mov.b64 %0, {%1, %2};" : "=l"(r) : "f"(x), "f"(y)); return r;
}
__device__ __forceinline__ void fma2(u64 &d, u64 a, u64 b) {
    asm("fma.rn.f32x2 %0, %1, %2, %3;" : "=l"(d) : "l"(a), "l"(b), "l"(d));
}
__device__ __forceinline__ float2 unpack2(u64 v) {
    float2 f; asm("mov.b64 {%0, %1}, %2;" : "=f"(f.x), "=f"(f.y) : "l"(v)); return f;
}

// ------------- block reductions -------------
template<int NT>
__device__ __forceinline__ float blkSum(float v) {
    __shared__ float sh[NT/32];
    int lane = threadIdx.x & 31, w = threadIdx.x >> 5;
    #pragma unroll
    for (int o = 16; o; o >>= 1) v += __shfl_down_sync(0xffffffffu, v, o);
    __syncthreads();
    if (!lane) sh[w] = v;
    __syncthreads();
    if (!w) {
        float x = (lane < NT/32) ? sh[lane] : 0.f;
        #pragma unroll
        for (int o = 16; o; o >>= 1) x += __shfl_down_sync(0xffffffffu, x, o);
        if (!lane) sh[0] = x;
    }
    __syncthreads();
    return sh[0];
}
template<int NT>
__device__ __forceinline__ float blkMax(float v) {
    __shared__ float sh[NT/32];
    int lane = threadIdx.x & 31, w = threadIdx.x >> 5;
    #pragma unroll
    for (int o = 16; o; o >>= 1) v = fmaxf(v, __shfl_down_sync(0xffffffffu, v, o));
    __syncthreads();
    if (!lane) sh[w] = v;
    __syncthreads();
    if (!w) {
        float x = (lane < NT/32) ? sh[lane] : -1e30f;
        #pragma unroll
        for (int o = 16; o; o >>= 1) x = fmaxf(x, __shfl_down_sync(0xffffffffu, x, o));
        if (!lane) sh[0] = x;
    }
    __syncthreads();
    return sh[0];
}

// ------------- 1) LN stats of query + gates softmax -------------
__global__ void k_prep(const float* __restrict__ q, const float* __restrict__ wg) {
    int b = blockIdx.x, t = threadIdx.x;           // 16 x 512
    float v = q[b*DD + t];
    float mu  = blkSum<512>(v)   * (1.f/DD);
    float msq = blkSum<512>(v*v) * (1.f/DD);
    float rs = rsqrtf(msq - mu*mu + 1e-5f);
    g_xn[b*DD + t] = (v - mu) * rs;

    float le[EE];
    #pragma unroll
    for (int e = 0; e < EE; ++e) le[e] = v * wg[t*EE + e];
    #pragma unroll
    for (int e = 0; e < EE; ++e)
        #pragma unroll
        for (int o = 16; o; o >>= 1) le[e] += __shfl_down_sync(0xffffffffu, le[e], o);
    __shared__ float sge[16][EE];
    int lane = t & 31, w = t >> 5;
    if (!lane)
        #pragma unroll
        for (int e = 0; e < EE; ++e) sge[w][e] = le[e];
    __syncthreads();
    if (t == 0) {
        float lg[EE];
        #pragma unroll
        for (int e = 0; e < EE; ++e) {
            float s = 0.f;
            #pragma unroll
            for (int w2 = 0; w2 < 16; ++w2) s += sge[w2][e];
            lg[e] = s;
        }
        float m = lg[0];
        #pragma unroll
        for (int e = 1; e < EE; ++e) m = fmaxf(m, lg[e]);
        float s = 0.f, ex[EE];
        #pragma unroll
        for (int e = 0; e < EE; ++e) { ex[e] = expf(lg[e] - m); s += ex[e]; }
        float inv = 1.f / s;
        #pragma unroll
        for (int e = 0; e < EE; ++e) g_gates[b*EE + e] = ex[e] * inv;
    }
}

// ------------- 1b) qn = xn * g + b -------------
__global__ void k_qn(const float* __restrict__ g, const float* __restrict__ bb) {
    int blk = blockIdx.x, t = threadIdx.x;         // 128 x 512
    int b = blk >> 3, e = blk & 7;
    g_qn[(b*EE+e)*DD + t] = g_xn[b*DD + t] * g[e*DD + t] + bb[e*DD + t];
}

// ------------- generic split-K weight-streaming GEMM (M=16) -------------
// out partial P[((s*BB+b)*EE+e)*N + n] ; X[((b*EE+e)*XH + h)*K + k]
// grid (N/256, EE, K/Kc), block 128. Each thread: 2 consecutive n, all 16 b.
__global__ void __launch_bounds__(128) k_gemmW(
        const float* __restrict__ X, const float* __restrict__ W,
        float* __restrict__ P, int K, int N, int Kc, int XH) {
    int n0 = blockIdx.x * 256, e = blockIdx.y, s = blockIdx.z;
    int ks0 = s * Kc, t = threadIdx.x;
    __shared__ __align__(16) float sX[4096];       // [(h*Kc + k)*16 + b]
    int fillN = XH * Kc * 16;
    for (int i = t; i < fillN; i += 128) {
        int b = i & 15, hk = i >> 4;
        int k = hk % Kc, h = hk / Kc;
        sX[(h*Kc + k)*16 + b] = X[((size_t)(b*EE + e)*XH + h)*K + ks0 + k];
    }
    __syncthreads();
    int w = t >> 5;
    const float* sXh = sX + ((XH == 8) ? ((n0 >> 6) + w) * Kc * 16 : 0);
    const float* wp = W + ((size_t)e*K + ks0)*N + n0 + 2*t;
    u64 acc0[8], acc1[8];
    #pragma unroll
    for (int i = 0; i < 8; ++i) { acc0[i] = 0ull; acc1[i] = 0ull; }

    for (int k0 = 0; k0 < Kc; k0 += 8) {
        float2 wb[8];
        #pragma unroll
        for (int i = 0; i < 8; ++i)
            wb[i] = *reinterpret_cast<const float2*>(wp + (size_t)(k0 + i)*N);
        #pragma unroll
        for (int i = 0; i < 8; ++i) {
            u64 w0 = pack2(wb[i].x, wb[i].x);
            u64 w1 = pack2(wb[i].y, wb[i].y);
            const u64* xr = reinterpret_cast<const u64*>(sXh + (k0 + i)*16);
            #pragma unroll
            for (int bp = 0; bp < 8; ++bp) {
                u64 xx = xr[bp];
                fma2(acc0[bp], xx, w0);
                fma2(acc1[bp], xx, w1);
            }
        }
    }
    int n = n0 + 2*t;
    size_t base = (size_t)s*BB*EE*N;
    #pragma unroll
    for (int bp = 0; bp < 8; ++bp) {
        float2 v0 = unpack2(acc0[bp]);
        float2 v1 = unpack2(acc1[bp]);
        size_t r0 = base + ((size_t)(2*bp)*EE + e)*N + n;
        size_t r1 = base + ((size_t)(2*bp + 1)*EE + e)*N + n;
        P[r0] = v0.x; P[r0 + 1] = v1.x;
        P[r1] = v0.y; P[r1 + 1] = v1.y;
    }
}

// ------------- reduce partials + bias (+gelu) (+resid) -------------
__global__ void k_red(const float* __restrict__ P, const float* __restrict__ bias,
                      const float* __restrict__ resid, float* __restrict__ Y,
                      int N, int S, int act) {
    int i = blockIdx.x * 256 + threadIdx.x;
    int BEN = BB*EE*N;
    if (i >= BEN) return;
    float s = 0.f;
    for (int sl = 0; sl < S; ++sl) s += P[(size_t)sl*BEN + i];
    int n = i % N, e = (i / N) & 7;
    s += bias[e*N + n];
    if (act) s = 0.5f * s * (1.f + erff(s * 0.70710678118654752f));
    if (resid) s += resid[i];
    Y[i] = s;
}

// ------------- qt[b,eh,d] = 0.125 * sum_c qh[b,e,h*64+c] * Wk[e,d,h*64+c] -------------
__global__ void __launch_bounds__(128) k_qt(const float* __restrict__ Wk) {
    int d0 = blockIdx.x * 128, eh = blockIdx.y;    // (4, 64) x 128
    int e = eh >> 3, h = eh & 7, t = threadIdx.x;
    __shared__ __align__(16) float sQ[64*16];      // [c*16 + b]
    for (int i = t; i < 1024; i += 128) {
        int b = i & 15, c = i >> 4;
        sQ[c*16 + b] = g_qh[((size_t)b*EE + e)*DD + h*64 + c];
    }
    __syncthreads();
    int d = d0 + t;
    const float4* wr = reinterpret_cast<const float4*>(Wk + ((size_t)e*DD + d)*DD + h*64);
    u64 acc[8];
    #pragma unroll
    for (int i = 0; i < 8; ++i) acc[i] = 0ull;
    #pragma unroll 4
    for (int c4 = 0; c4 < 16; ++c4) {
        float4 wv = wr[c4];
        float wa[4] = {wv.x, wv.y, wv.z, wv.w};
        #pragma unroll
        for (int j = 0; j < 4; ++j) {
            u64 wd = pack2(wa[j], wa[j]);
            const u64* q = reinterpret_cast<const u64*>(sQ + (c4*4 + j)*16);
            #pragma unroll
            for (int bp = 0; bp < 8; ++bp) fma2(acc[bp], q[bp], wd);
        }
    }
    #pragma unroll
    for (int bp = 0; bp < 8; ++bp) {
        float2 v = unpack2(acc[bp]);
        g_qt[((size_t)(2*bp)*EHD + eh)*DD + d]     = 0.125f * v.x;
        g_qt[((size_t)(2*bp + 1)*EHD + eh)*DD + d] = 0.125f * v.y;
    }
}

// ------------- scores[b,eh,l] = retr[b,l,:] . qt[b,eh,:] -------------
__global__ void __launch_bounds__(128) k_scores(const float* __restrict__ retr) {
    int l0 = blockIdx.x * 128, b = blockIdx.y, t = threadIdx.x;  // (16,16) x 128
    __shared__ __align__(16) float sA[32*130];     // [k][l] pad 130
    __shared__ u64 sB[32*65];                      // [k][eh] dup pad 65
    int ehg = t & 7, lg = t >> 3;                  // 8 ehg x 16 lg
    u64 acc[4][8];
    #pragma unroll
    for (int i = 0; i < 4; ++i)
        #pragma unroll
        for (int j = 0; j < 8; ++j) acc[i][j] = 0ull;

    for (int k0 = 0; k0 < DD; k0 += 32) {
        {
            int l = t;
            const float4* rp = reinterpret_cast<const float4*>(
                retr + ((size_t)b*LL + l0 + l)*DD + k0);
            #pragma unroll
            for (int q = 0; q < 8; ++q) {
                float4 v = rp[q];
                sA[(q*4 + 0)*130 + l] = v.x;
                sA[(q*4 + 1)*130 + l] = v.y;
                sA[(q*4 + 2)*130 + l] = v.z;
                sA[(q*4 + 3)*130 + l] = v.w;
            }
        }
        for (int i = t; i < 2048; i += 128) {
            int k = i & 31, eh = i >> 5;
            float v = g_qt[((size_t)b*EHD + eh)*DD + k0 + k];
            sB[k*65 + eh] = pack2(v, v);
        }
        __syncthreads();
        #pragma unroll 4
        for (int k = 0; k < 32; ++k) {
            u64 bbv[8];
            #pragma unroll
            for (int j = 0; j < 8; ++j) bbv[j] = sB[k*65 + ehg*8 + j];
            #pragma unroll
            for (int i = 0; i < 4; ++i) {
                u64 aa = *reinterpret_cast<const u64*>(&sA[k*130 + lg*8 + 2*i]);
                #pragma unroll
                for (int j = 0; j < 8; ++j) fma2(acc[i][j], aa, bbv[j]);
            }
        }
        __syncthreads();
    }
    #pragma unroll
    for (int i = 0; i < 4; ++i)
        #pragma unroll
        for (int j = 0; j < 8; ++j) {
            float2 v = unpack2(acc[i][j]);
            int l = l0 + lg*8 + 2*i, eh = ehg*8 + j;
            g_scores[((size_t)b*EHD + eh)*LL + l]     = v.x;
            g_scores[((size_t)b*EHD + eh)*LL + l + 1] = v.y;
        }
}

// ------------- softmax over L, in place (registers only) -------------
__global__ void k_softmax() {
    int r = blockIdx.x, t = threadIdx.x;           // 1024 x 256
    float* base = g_scores + (size_t)r * LL;
    float v[8];
    #pragma unroll
    for (int i = 0; i < 8; ++i) v[i] = base[t + 256*i];
    float m = v[0];
    #pragma unroll
    for (int i = 1; i < 8; ++i) m = fmaxf(m, v[i]);
    m = blkMax<256>(m);
    float s = 0.f;
    #pragma unroll
    for (int i = 0; i < 8; ++i) { v[i] = __expf(v[i] - m); s += v[i]; }
    s = blkSum<256>(s);
    float inv = 1.f / s;
    #pragma unroll
    for (int i = 0; i < 8; ++i) base[t + 256*i] = v[i] * inv;
}

// ------------- entropy of head-averaged probs -------------
__global__ void k_entropy() {
    int be = blockIdx.x, t = threadIdx.x;          // 128 x 256
    int b = be >> 3, e = be & 7;
    const float* base = g_scores + (((size_t)b*EHD) + e*8) * LL;
    float acc = 0.f;
    for (int l = t; l < LL; l += 256) {
        float s = 0.f;
        #pragma unroll
        for (int h = 0; h < HH; ++h) s += base[(size_t)h*LL + l];
        float p = fmaxf(s * 0.125f, 1e-12f);
        acc += p * __logf(p);
    }
    acc = blkSum<256>(acc);
    if (t == 0) g_ent[be] = -acc;
}

// ------------- ctx partials: cpart[ls][b][eh][d] over L-chunks of 512 -------------
__global__ void __launch_bounds__(128) k_ctx(const float* __restrict__ retr) {
    int d0 = blockIdx.x*128, b = blockIdx.y, ls = blockIdx.z, t = threadIdx.x; // (4,16,4)x128
    __shared__ __align__(16) float sR[32*132];     // [l][d] pad 132
    __shared__ u64 sP[32*65];                      // [l][eh] dup pad 65
    int ehg = t & 7, dg = t >> 3;                  // 8 ehg x 16 dg
    u64 acc[4][8];
    #pragma unroll
    for (int i = 0; i < 4; ++i)
        #pragma unroll
        for (int j = 0; j < 8; ++j) acc[i][j] = 0ull;

    for (int kt = 0; kt < 16; ++kt) {
        int lbase = ls*512 + kt*32;
        {
            int l = t & 31, dchunk = t >> 5;       // 32 l x 4 chunks of 32 d
            const float4* rp = reinterpret_cast<const float4*>(
                retr + ((size_t)b*LL + lbase + l)*DD + d0 + dchunk*32);
            float* dst = sR + l*132 + dchunk*32;
            #pragma unroll
            for (int q = 0; q < 8; ++q)
                *reinterpret_cast<float4*>(dst + 4*q) = rp[q];
        }
        for (int i = t; i < 2048; i += 128) {
            int l = i & 31, eh = i >> 5;
            float v = g_scores[((size_t)b*EHD + eh)*LL + lbase + l];
            sP[l*65 + eh] = pack2(v, v);
        }
        __syncthreads();
        #pragma unroll 4
        for (int l = 0; l < 32; ++l) {
            u64 pv[8];
            #pragma unroll
            for (int j = 0; j < 8; ++j) pv[j] = sP[l*65 + ehg*8 + j];
            #pragma unroll
            for (int i = 0; i < 4; ++i) {
                u64 rr = *reinterpret_cast<const u64*>(&sR[l*132 + dg*8 + 2*i]);
                #pragma unroll
                for (int j = 0; j < 8; ++j) fma2(acc[i][j], pv[j], rr);
            }
        }
        __syncthreads();
    }
    #pragma unroll
    for (int i = 0; i < 4; ++i)
        #pragma unroll
        for (int j = 0; j < 8; ++j) {
            float2 v = unpack2(acc[i][j]);
            int d = d0 + dg*8 + 2*i, eh = ehg*8 + j;
            float* p = g_cpart + (((size_t)ls*BB + b)*EHD + eh)*DD + d;
            p[0] = v.x; p[1] = v.y;
        }
}

// ------------- sum ctx partials -------------
__global__ void k_credux() {
    int i = blockIdx.x * 256 + threadIdx.x;        // 512K elems
    if (i >= BB*EHD*DD) return;
    float s = 0.f;
    #pragma unroll
    for (int ls = 0; ls < 4; ++ls) s += g_cpart[(size_t)ls*BB*EHD*DD + i];
    g_ctx[i] = s;
}

// ------------- x = query + attn_out ; xo = LN(x) affine -------------
__global__ void k_xln(const float* __restrict__ q, const float* __restrict__ g,
                      const float* __restrict__ bb) {
    int blk = blockIdx.x, t = threadIdx.x;         // 128 x 512
    int b = blk >> 3, e = blk & 7;
    float x = q[b*DD + t] + g_ao[((size_t)b*EE + e)*DD + t];
    g_x[((size_t)b*EE + e)*DD + t] = x;
    float mu  = blkSum<512>(x)   * (1.f/DD);
    float msq = blkSum<512>(x*x) * (1.f/DD);
    float rs = rsqrtf(msq - mu*mu + 1e-5f);
    g_xo[((size_t)b*EE + e)*DD + t] = (x - mu) * rs * g[e*DD + t] + bb[e*DD + t];
}

// ------------- gating mix + output -------------
__global__ void k_final(const float* __restrict__ y, float* __restrict__ out, int out_size) {
    int b = blockIdx.x, t = threadIdx.x;           // 16 x 512
    __shared__ float sgt[EE];
    if (t == 0) {
        float gt[EE], s = 0.f;
        #pragma unroll
        for (int e = 0; e < EE; ++e) {
            gt[e] = g_gates[b*EE + e] * expf(-0.5f * g_ent[b*EE + e]);
            s += gt[e];
        }
        float inv = 1.f / (s + 1e-9f);
        #pragma unroll
        for (int e = 0; e < EE; ++e) sgt[e] = gt[e] * inv;
    }
    __syncthreads();
    float m = 0.f;
    #pragma unroll
    for (int e = 0; e < EE; ++e) m += sgt[e] * y[((size_t)b*EE + e)*DD + t];
    out[b*DD + t] = m;
    if (out_size >= BB*DD + BB*EE*DD + BB*EE) {
        if (t < EE) out[BB*DD + BB*EE*DD + b*EE + t] = sgt[t];
    }
}

// ------------- host -------------
extern "C" void kernel_launch(void* const* d_in, const int* in_sizes, int n_in,
                              void* d_out, int out_size) {
    const float* query = (const float*)d_in[0];
    const float* retr  = (const float*)d_in[1];
    const float* wgate = (const float*)d_in[2];
    const float* lnqg  = (const float*)d_in[3];
    const float* lnqb  = (const float*)d_in[4];
    const float* Wq    = (const float*)d_in[5];
    const float* bq    = (const float*)d_in[6];
    const float* Wk    = (const float*)d_in[7];
    const float* Wv    = (const float*)d_in[9];
    const float* bv    = (const float*)d_in[10];
    const float* Wo    = (const float*)d_in[11];
    const float* bo    = (const float*)d_in[12];
    const float* lnog  = (const float*)d_in[13];
    const float* lnob  = (const float*)d_in[14];
    const float* W1    = (const float*)d_in[15];
    const float* b1    = (const float*)d_in[16];
    const float* W2    = (const float*)d_in[17];
    const float* b2    = (const float*)d_in[18];
    float* out = (float*)d_out;

    void *p_qn, *p_qh, *p_ctx, *p_attn, *p_ao, *p_x, *p_xo, *p_h, *p_y, *p_part;
    cudaGetSymbolAddress(&p_qn, g_qn);
    cudaGetSymbolAddress(&p_qh, g_qh);
    cudaGetSymbolAddress(&p_ctx, g_ctx);
    cudaGetSymbolAddress(&p_attn, g_attn);
    cudaGetSymbolAddress(&p_ao, g_ao);
    cudaGetSymbolAddress(&p_x, g_x);
    cudaGetSymbolAddress(&p_xo, g_xo);
    cudaGetSymbolAddress(&p_h, g_h);
    cudaGetSymbolAddress(&p_y, g_y);
    cudaGetSymbolAddress(&p_part, g_part);
    float* part = (float*)p_part;
    float* yptr = (out_size >= BB*DD + BB*EE*DD) ? (out + BB*DD) : (float*)p_y;

    k_prep<<<BB, 512>>>(query, wgate);
    k_qn<<<BB*EE, 512>>>(lnqg, lnqb);

    // qh = qn @ Wq + bq
    k_gemmW<<<dim3(2, EE, 16), 128>>>((const float*)p_qn, Wq, part, DD, DD, 32, 1);
    k_red<<<256, 256>>>(part, bq, nullptr, (float*)p_qh, DD, 16, 0);

    k_qt<<<dim3(4, 64), 128>>>(Wk);
    k_scores<<<dim3(16, BB), 128>>>(retr);
    k_softmax<<<BB*EHD, 256>>>();
    k_entropy<<<BB*EE, 256>>>();
    k_ctx<<<dim3(4, BB, 4), 128>>>(retr);
    k_credux<<<BB*EHD*DD/256, 256>>>();

    // attn = ctx @ Wv(+per-h) + bv
    k_gemmW<<<dim3(2, EE, 16), 128>>>((const float*)p_ctx, Wv, part, DD, DD, 32, 8);
    k_red<<<256, 256>>>(part, bv, nullptr, (float*)p_attn, DD, 16, 0);

    // ao = attn @ Wo + bo
    k_gemmW<<<dim3(2, EE, 16), 128>>>((const float*)p_attn, Wo, part, DD, DD, 32, 1);
    k_red<<<256, 256>>>(part, bo, nullptr, (float*)p_ao, DD, 16, 0);

    k_xln<<<BB*EE, 512>>>(query, lnog, lnob);

    // h = gelu(xo @ W1 + b1)
    k_gemmW<<<dim3(8, EE, 8), 128>>>((const float*)p_xo, W1, part, DD, FF, 64, 1);
    k_red<<<1024, 256>>>(part, b1, nullptr, (float*)p_h, FF, 8, 1);

    // y = h @ W2 + b2 + x
    k_gemmW<<<dim3(2, EE, 16), 128>>>((const float*)p_h, W2, part, FF, DD, 128, 1);
    k_red<<<256, 256>>>(part, b2, (const float*)p_x, yptr, DD, 16, 0);

    k_final<<<BB, 512>>>(yptr, out, out_size);
}